// round 7
// baseline (speedup 1.0000x reference)
#include <cuda_runtime.h>

#define NC 256
#define FH 38
#define FW 38
#define NHW (FH * FW)       // 1444
#define PPH 7
#define PPW 7
#define NBINS (PPH * PPW)   // 49
#define OUT_PER_ROI (NC * NBINS)  // 12544

// Transposed features: [H][W][C], channel-contiguous for coalesced warp reads.
__device__ float g_ft[NHW * NC];

// Tiled transpose: features (C, H*W) -> g_ft (H*W, C). Both GMEM sides coalesced.
__global__ void transpose_kernel(const float* __restrict__ f) {
    __shared__ float t[32][33];
    const int hw0 = blockIdx.x * 32;
    const int c0  = blockIdx.y * 32;

    int hw = hw0 + threadIdx.x;
    int c  = c0 + threadIdx.y;
    if (hw < NHW) t[threadIdx.y][threadIdx.x] = f[c * NHW + hw];
    __syncthreads();

    int hw2 = hw0 + threadIdx.y;
    int c2  = c0 + threadIdx.x;
    if (hw2 < NHW) g_ft[hw2 * NC + c2] = t[threadIdx.x][threadIdx.y];
}

__global__ void pool_kernel(const float* __restrict__ rois,
                            const float* __restrict__ sscale,
                            float* __restrict__ out) {
    extern __shared__ float s_out[];  // [NC][NBINS] = 50176 B

    const int roi = blockIdx.x;
    const int tid = threadIdx.x;      // channel; warp = 32 consecutive channels
    const float scale = *sscale;

    const float* r = rois + roi * 5;
    // jnp.round = half-to-even = rintf (scale=1/16: product exact)
    const int x1 = (int)rintf(__fmul_rn(r[1], scale));
    const int y1 = (int)rintf(__fmul_rn(r[2], scale));
    const int x2 = (int)rintf(__fmul_rn(r[3], scale));
    const int y2 = (int)rintf(__fmul_rn(r[4], scale));

    // CRITICAL: XLA rewrites (w / 7) to (w * RN(1/7)). Match bit-for-bit by
    // multiplying with the correctly-rounded f32 reciprocal, NOT dividing.
    const float RCP7 = 1.0f / 7.0f;   // 0x3E124925
    const float bw = __fmul_rn((float)max(x2 - x1 + 1, 1), RCP7);
    const float bh = __fmul_rn((float)max(y2 - y1 + 1, 1), RCP7);

    const float NEG_INF = __int_as_float(0xff800000);
    const float* base = g_ft + tid;

    #pragma unroll 1
    for (int ph = 0; ph < PPH; ++ph) {
        int hs = (int)floorf(__fmul_rn((float)ph, bh));
        int he = (int)ceilf(__fmul_rn((float)(ph + 1), bh));
        hs = min(max(hs + y1, 0), FH);
        he = min(max(he + y1, 0), FH);

        #pragma unroll 1
        for (int pw = 0; pw < PPW; ++pw) {
            int ws = (int)floorf(__fmul_rn((float)pw, bw));
            int we = (int)ceilf(__fmul_rn((float)(pw + 1), bw));
            ws = min(max(ws + x1, 0), FW);
            we = min(max(we + x1, 0), FW);

            float m = NEG_INF;
            for (int h = hs; h < he; ++h) {
                const float* rowp = base + (h * FW) * NC;
                #pragma unroll 1
                for (int w = ws; w < we; ++w) {
                    m = fmaxf(m, rowp[w * NC]);
                }
            }
            if (he <= hs || we <= ws) m = 0.0f;   // empty bin -> 0

            // lane stride 49 words -> bank stride 17 mod 32 -> conflict-free
            s_out[tid * NBINS + ph * PPW + pw] = m;
        }
    }

    __syncthreads();

    // Fully coalesced write of this roi's 12544 contiguous floats
    float* o = out + roi * OUT_PER_ROI;
    #pragma unroll
    for (int i = 0; i < OUT_PER_ROI / 256; ++i) {  // 49 iterations
        int idx = tid + i * 256;
        o[idx] = s_out[idx];
    }
}

extern "C" void kernel_launch(void* const* d_in, const int* in_sizes, int n_in,
                              void* d_out, int out_size) {
    const float* features = (const float*)d_in[0];
    const float* rois     = (const float*)d_in[1];
    const float* sscale   = (const float*)d_in[2];
    float* out = (float*)d_out;

    const int n_rois = in_sizes[1] / 5;

    dim3 tgrid((NHW + 31) / 32, NC / 32);
    transpose_kernel<<<tgrid, dim3(32, 32)>>>(features);

    const int smem = OUT_PER_ROI * (int)sizeof(float);  // 50176 B > 48KB default
    cudaFuncSetAttribute(pool_kernel, cudaFuncAttributeMaxDynamicSharedMemorySize, smem);
    pool_kernel<<<n_rois, NC, smem>>>(rois, sscale, out);
}

// round 8
// speedup vs baseline: 2.4611x; 2.4611x over previous
#include <cuda_runtime.h>

#define NC 256
#define FH 38
#define FW 38
#define NHW (FH * FW)       // 1444
#define PPH 7
#define PPW 7
#define NBINS (PPH * PPW)   // 49
#define OUT_PER_ROI (NC * NBINS)  // 12544

// Transposed features: [H][W][C], channel-contiguous for coalesced warp reads.
__device__ float g_ft[NHW * NC];

__global__ void transpose_kernel(const float* __restrict__ f) {
    __shared__ float t[32][33];
    const int hw0 = blockIdx.x * 32;
    const int c0  = blockIdx.y * 32;

    int hw = hw0 + threadIdx.x;
    int c  = c0 + threadIdx.y;
    if (hw < NHW) t[threadIdx.y][threadIdx.x] = f[c * NHW + hw];
    __syncthreads();

    int hw2 = hw0 + threadIdx.y;
    int c2  = c0 + threadIdx.x;
    if (hw2 < NHW) g_ft[hw2 * NC + c2] = t[threadIdx.x][threadIdx.y];
}

// One block per (roi, ph bin-row). Thread = channel. Each thread scans the
// row-union once with 7 accumulators (MLP-4 chunked loads).
__global__ void pool_kernel(const float* __restrict__ rois,
                            const float* __restrict__ sscale,
                            float* __restrict__ out) {
    __shared__ float s_out[NC * PPW];  // stride-7 layout: conflict-free (7 coprime 32)

    const int roi = blockIdx.x;
    const int ph  = blockIdx.y;
    const int c   = threadIdx.x;
    const float scale = *sscale;

    const float* r = rois + roi * 5;
    // jnp.round = half-to-even = rintf
    const int x1 = (int)rintf(__fmul_rn(r[1], scale));
    const int y1 = (int)rintf(__fmul_rn(r[2], scale));
    const int x2 = (int)rintf(__fmul_rn(r[3], scale));
    const int y2 = (int)rintf(__fmul_rn(r[4], scale));

    // Match XLA: w/7 lowered to w * RN(1/7)
    const float RCP7 = 1.0f / 7.0f;
    const float bw = __fmul_rn((float)max(x2 - x1 + 1, 1), RCP7);
    const float bh = __fmul_rn((float)max(y2 - y1 + 1, 1), RCP7);

    int hs = (int)floorf(__fmul_rn((float)ph, bh));
    int he = (int)ceilf(__fmul_rn((float)(ph + 1), bh));
    hs = min(max(hs + y1, 0), FH);
    he = min(max(he + y1, 0), FH);

    int ws[PPW], we[PPW];
    #pragma unroll
    for (int p = 0; p < PPW; ++p) {
        int a = (int)floorf(__fmul_rn((float)p, bw));
        int b = (int)ceilf(__fmul_rn((float)(p + 1), bw));
        ws[p] = min(max(a + x1, 0), FW);
        we[p] = min(max(b + x1, 0), FW);
    }
    const int wlo = ws[0];        // monotone non-decreasing after clip
    const int whi = we[PPW - 1];

    const float NEG_INF = __int_as_float(0xff800000);
    float m[PPW];
    #pragma unroll
    for (int p = 0; p < PPW; ++p) m[p] = NEG_INF;

    const float* base = g_ft + c;

    if (he > hs && whi > wlo) {
        for (int h = hs; h < he; ++h) {
            const float* rowp = base + (h * FW) * NC;
            for (int w0 = wlo; w0 < whi; w0 += 4) {
                // 4 independent loads issued back-to-back (clamped dup is safe)
                float v0 = rowp[min(w0 + 0, whi - 1) * NC];
                float v1 = rowp[min(w0 + 1, whi - 1) * NC];
                float v2 = rowp[min(w0 + 2, whi - 1) * NC];
                float v3 = rowp[min(w0 + 3, whi - 1) * NC];
                #pragma unroll
                for (int j = 0; j < 4; ++j) {
                    int w = w0 + j;
                    float v = (j == 0) ? v0 : (j == 1) ? v1 : (j == 2) ? v2 : v3;
                    if (w < whi) {
                        #pragma unroll
                        for (int p = 0; p < PPW; ++p) {
                            if (w >= ws[p] && w < we[p]) m[p] = fmaxf(m[p], v);
                        }
                    }
                }
            }
        }
    }

    const bool row_empty = (he <= hs);
    #pragma unroll
    for (int p = 0; p < PPW; ++p) {
        float v = (row_empty || we[p] <= ws[p]) ? 0.0f : m[p];
        s_out[c * PPW + p] = v;
    }

    __syncthreads();

    // Write 1792 floats: out[roi][ch][ph*7 + pw]
    const int out_base = roi * OUT_PER_ROI + ph * PPW;
    #pragma unroll
    for (int k = 0; k < PPW; ++k) {           // 7 iterations of 256 threads
        int i  = k * NC + c;                  // 0..1791
        int ch = i / PPW;
        int pw = i - ch * PPW;
        out[out_base + ch * NBINS + pw] = s_out[i];
    }
}

extern "C" void kernel_launch(void* const* d_in, const int* in_sizes, int n_in,
                              void* d_out, int out_size) {
    const float* features = (const float*)d_in[0];
    const float* rois     = (const float*)d_in[1];
    const float* sscale   = (const float*)d_in[2];
    float* out = (float*)d_out;

    const int n_rois = in_sizes[1] / 5;

    dim3 tgrid((NHW + 31) / 32, NC / 32);
    transpose_kernel<<<tgrid, dim3(32, 32)>>>(features);

    pool_kernel<<<dim3(n_rois, PPH), NC>>>(rois, sscale, out);
}

// round 10
// speedup vs baseline: 6.3081x; 2.5631x over previous
#include <cuda_runtime.h>

#define NC 256
#define FH 38
#define FW 38
#define NHW (FH * FW)       // 1444
#define PPH 7
#define PPW 7
#define NBINS (PPH * PPW)   // 49
#define OUT_PER_ROI (NC * NBINS)  // 12544

// Transposed features: [H][W][C], channel-contiguous for coalesced warp reads.
__device__ float g_ft[NHW * NC];

__global__ void transpose_kernel(const float* __restrict__ f) {
    __shared__ float t[32][33];
    const int hw0 = blockIdx.x * 32;
    const int c0  = blockIdx.y * 32;

    int hw = hw0 + threadIdx.x;
    int c  = c0 + threadIdx.y;
    if (hw < NHW) t[threadIdx.y][threadIdx.x] = f[c * NHW + hw];
    __syncthreads();

    int hw2 = hw0 + threadIdx.y;
    int c2  = c0 + threadIdx.x;
    if (hw2 < NHW) g_ft[hw2 * NC + c2] = t[threadIdx.x][threadIdx.y];
}

// One block per (roi, ph bin-row). Thread = channel.
// Column-scan factorization: per column compute max over h once (colmax),
// then one 7-bin predicated update per COLUMN (not per load).
__global__ void pool_kernel(const float* __restrict__ rois,
                            const float* __restrict__ sscale,
                            float* __restrict__ out) {
    __shared__ float s_out[NC * PPW];

    const int roi = blockIdx.x;
    const int ph  = blockIdx.y;
    const int c   = threadIdx.x;
    const float scale = *sscale;

    const float* r = rois + roi * 5;
    // jnp.round = half-to-even = rintf
    const int x1 = (int)rintf(__fmul_rn(r[1], scale));
    const int y1 = (int)rintf(__fmul_rn(r[2], scale));
    const int x2 = (int)rintf(__fmul_rn(r[3], scale));
    const int y2 = (int)rintf(__fmul_rn(r[4], scale));

    // Match XLA: w/7 lowered to w * RN(1/7)
    const float RCP7 = 1.0f / 7.0f;
    const float bw = __fmul_rn((float)max(x2 - x1 + 1, 1), RCP7);
    const float bh = __fmul_rn((float)max(y2 - y1 + 1, 1), RCP7);

    int hs = (int)floorf(__fmul_rn((float)ph, bh));
    int he = (int)ceilf(__fmul_rn((float)(ph + 1), bh));
    hs = min(max(hs + y1, 0), FH);
    he = min(max(he + y1, 0), FH);

    int ws[PPW], we[PPW];
    #pragma unroll
    for (int p = 0; p < PPW; ++p) {
        int a = (int)floorf(__fmul_rn((float)p, bw));
        int b = (int)ceilf(__fmul_rn((float)(p + 1), bw));
        ws[p] = min(max(a + x1, 0), FW);
        we[p] = min(max(b + x1, 0), FW);
    }
    const int wlo = ws[0];        // monotone non-decreasing after clip
    const int whi = we[PPW - 1];

    const float NEG_INF = __int_as_float(0xff800000);
    float m[PPW];
    #pragma unroll
    for (int p = 0; p < PPW; ++p) m[p] = NEG_INF;

    const float* base = g_ft + c;

    if (he > hs) {
        // Walk union columns in pairs; per column: fmax-reduce over h,
        // then a single 7-bin predicated update.
        for (int w = wlo; w < whi; w += 2) {
            const int w1 = min(w + 1, whi - 1);   // clamp once per pair
            const float* p0 = base + (hs * FW + w)  * NC;
            const float* p1 = base + (hs * FW + w1) * NC;
            float cm0 = NEG_INF, cm1 = NEG_INF;
            for (int h = hs; h < he; ++h) {
                cm0 = fmaxf(cm0, *p0);
                cm1 = fmaxf(cm1, *p1);
                p0 += FW * NC;
                p1 += FW * NC;
            }
            #pragma unroll
            for (int p = 0; p < PPW; ++p) {
                if (w >= ws[p] && w < we[p]) m[p] = fmaxf(m[p], cm0);
            }
            if (w1 != w) {
                #pragma unroll
                for (int p = 0; p < PPW; ++p) {
                    if (w1 >= ws[p] && w1 < we[p]) m[p] = fmaxf(m[p], cm1);
                }
            }
        }
    }

    // Empty bins (no h rows or no w cols) -> 0. m[p]==NEG_INF iff never updated.
    #pragma unroll
    for (int p = 0; p < PPW; ++p) {
        float v = (he <= hs || we[p] <= ws[p]) ? 0.0f : m[p];
        s_out[c * PPW + p] = v;   // stride 7: coprime with 32 -> conflict-free
    }

    __syncthreads();

    // Coalesced write of this (roi, ph) slice: out[roi][ch][ph*7 + pw]
    const int out_base = roi * OUT_PER_ROI + ph * PPW;
    #pragma unroll
    for (int k = 0; k < PPW; ++k) {           // 7 x 256 threads = 1792 floats
        int i  = k * NC + c;
        int ch = i / PPW;
        int pw = i - ch * PPW;
        out[out_base + ch * NBINS + pw] = s_out[i];
    }
}

extern "C" void kernel_launch(void* const* d_in, const int* in_sizes, int n_in,
                              void* d_out, int out_size) {
    const float* features = (const float*)d_in[0];
    const float* rois     = (const float*)d_in[1];
    const float* sscale   = (const float*)d_in[2];
    float* out = (float*)d_out;

    const int n_rois = in_sizes[1] / 5;

    dim3 tgrid((NHW + 31) / 32, NC / 32);
    transpose_kernel<<<tgrid, dim3(32, 32)>>>(features);

    pool_kernel<<<dim3(n_rois, PPH), NC>>>(rois, sscale, out);
}

// round 11
// speedup vs baseline: 7.9474x; 1.2599x over previous
#include <cuda_runtime.h>

#define NC 256
#define NCG (NC / 2)        // 128 float2 channel-groups
#define FH 38
#define FW 38
#define NHW (FH * FW)       // 1444
#define PPH 7
#define PPW 7
#define NBINS (PPH * PPW)   // 49
#define OUT_PER_ROI (NC * NBINS)  // 12544

// Transposed features: [H][W][C], channel-contiguous for coalesced warp reads.
__device__ float g_ft[NHW * NC];

__global__ void transpose_kernel(const float* __restrict__ f) {
    __shared__ float t[32][33];
    const int hw0 = blockIdx.x * 32;
    const int c0  = blockIdx.y * 32;

    int hw = hw0 + threadIdx.x;
    int c  = c0 + threadIdx.y;
    if (hw < NHW) t[threadIdx.y][threadIdx.x] = f[c * NHW + hw];
    __syncthreads();

    int hw2 = hw0 + threadIdx.y;
    int c2  = c0 + threadIdx.x;
    if (hw2 < NHW) g_ft[hw2 * NC + c2] = t[threadIdx.x][threadIdx.y];
}

// One block per (roi, ph). Thread = 2 channels (float2).
// Bins-outer / columns-inner: bin column ranges are disjoint up to <=1
// overlap column, so NO membership predicates are needed at all.
__global__ void pool_kernel(const float* __restrict__ rois,
                            const float* __restrict__ sscale,
                            float* __restrict__ out) {
    __shared__ float s_out[NC * PPW];   // 7168 B

    const int roi = blockIdx.x;
    const int ph  = blockIdx.y;
    const int cg  = threadIdx.x;        // channel group: channels 2cg, 2cg+1
    const float scale = *sscale;

    const float* r = rois + roi * 5;
    // jnp.round = half-to-even = rintf
    const int x1 = (int)rintf(__fmul_rn(r[1], scale));
    const int y1 = (int)rintf(__fmul_rn(r[2], scale));
    const int x2 = (int)rintf(__fmul_rn(r[3], scale));
    const int y2 = (int)rintf(__fmul_rn(r[4], scale));

    // Match XLA: w/7 lowered to w * RN(1/7)
    const float RCP7 = 1.0f / 7.0f;
    const float bw = __fmul_rn((float)max(x2 - x1 + 1, 1), RCP7);
    const float bh = __fmul_rn((float)max(y2 - y1 + 1, 1), RCP7);

    int hs = (int)floorf(__fmul_rn((float)ph, bh));
    int he = (int)ceilf(__fmul_rn((float)(ph + 1), bh));
    hs = min(max(hs + y1, 0), FH);
    he = min(max(he + y1, 0), FH);
    const int nh = he - hs;

    int ws[PPW], we[PPW];
    #pragma unroll
    for (int p = 0; p < PPW; ++p) {
        int a = (int)floorf(__fmul_rn((float)p, bw));
        int b = (int)ceilf(__fmul_rn((float)(p + 1), bw));
        ws[p] = min(max(a + x1, 0), FW);
        we[p] = min(max(b + x1, 0), FW);
    }

    const float NEG_INF = __int_as_float(0xff800000);
    const float2* base = (const float2*)g_ft + cg;   // this thread's 2 channels

    float2 m[PPW];

    #pragma unroll
    for (int p = 0; p < PPW; ++p) {
        float2 acc;
        acc.x = NEG_INF; acc.y = NEG_INF;
        if (nh > 0) {
            for (int w = ws[p]; w < we[p]; ++w) {
                const float2* q = base + (hs * FW + w) * NCG;
                #pragma unroll 2
                for (int h = 0; h < nh; ++h) {
                    float2 v = *q;
                    acc.x = fmaxf(acc.x, v.x);
                    acc.y = fmaxf(acc.y, v.y);
                    q += FW * NCG;
                }
            }
        }
        // empty bin (no rows or no cols) -> 0
        if (nh <= 0 || we[p] <= ws[p]) { acc.x = 0.0f; acc.y = 0.0f; }
        m[p] = acc;
    }

    #pragma unroll
    for (int p = 0; p < PPW; ++p) {
        s_out[(2 * cg + 0) * PPW + p] = m[p].x;
        s_out[(2 * cg + 1) * PPW + p] = m[p].y;
    }

    __syncthreads();

    // Coalesced write: out[roi][ch][ph*7 + pw], i = ch*7 + pw over 1792 floats
    const int out_base = roi * OUT_PER_ROI + ph * PPW;
    #pragma unroll
    for (int k = 0; k < 2 * PPW; ++k) {     // 14 iterations of 128 threads
        int i  = k * NCG + cg;
        int ch = i / PPW;
        int pw = i - ch * PPW;
        out[out_base + ch * NBINS + pw] = s_out[i];
    }
}

extern "C" void kernel_launch(void* const* d_in, const int* in_sizes, int n_in,
                              void* d_out, int out_size) {
    const float* features = (const float*)d_in[0];
    const float* rois     = (const float*)d_in[1];
    const float* sscale   = (const float*)d_in[2];
    float* out = (float*)d_out;

    const int n_rois = in_sizes[1] / 5;

    dim3 tgrid((NHW + 31) / 32, NC / 32);
    transpose_kernel<<<tgrid, dim3(32, 32)>>>(features);

    pool_kernel<<<dim3(n_rois, PPH), NCG>>>(rois, sscale, out);
}